// round 1
// baseline (speedup 1.0000x reference)
#include <cuda_runtime.h>
#include <math.h>
#include <float.h>

#define B_ROWS 4096
#define C_COLS 128
#define ROWS_PER_BLOCK 8
#define NBLOCKS (B_ROWS / ROWS_PER_BLOCK)   // 512

// Per-block partials: [bce_sum, wlsep_sum, pos_count] per block.
__device__ float g_partial[NBLOCKS * 3];

__device__ __forceinline__ float softplusf(float t) {
    // log(1 + exp(t)) stable
    float a = fabsf(t);
    return fmaxf(t, 0.0f) + log1pf(__expf(-a));
}

__device__ __forceinline__ float warp_sum(float v) {
    #pragma unroll
    for (int o = 16; o > 0; o >>= 1)
        v += __shfl_xor_sync(0xFFFFFFFFu, v, o);
    return v;
}

__device__ __forceinline__ float warp_max(float v) {
    #pragma unroll
    for (int o = 16; o > 0; o >>= 1)
        v = fmaxf(v, __shfl_xor_sync(0xFFFFFFFFu, v, o));
    return v;
}

// Kernel 1: one warp per row. blockDim = (32, ROWS_PER_BLOCK).
__global__ void __launch_bounds__(32 * ROWS_PER_BLOCK)
row_kernel(const float* __restrict__ x, const int* __restrict__ tgt) {
    const int row  = blockIdx.x * ROWS_PER_BLOCK + threadIdx.y;
    const int lane = threadIdx.x;

    const float* xr = x   + (size_t)row * C_COLS;
    const int*   tr = tgt + (size_t)row * C_COLS;

    float xs[4];
    int   ls[4];
    #pragma unroll
    for (int k = 0; k < 4; k++) {
        xs[k] = xr[lane + 32 * k];
        ls[k] = tr[lane + 32 * k];
    }

    // ---- BCE contribution + negative-class max ----
    float bce  = 0.0f;
    float mneg = -FLT_MAX;
    #pragma unroll
    for (int k = 0; k < 4; k++) {
        float t = ls[k] ? -xs[k] : xs[k];
        bce += softplusf(t);
        if (!ls[k]) mneg = fmaxf(mneg, xs[k]);
    }
    mneg = warp_max(mneg);   // row-wide max over negatives (-FLT_MAX if none)

    // ---- Z = sum over negatives of exp(x_i - M) ----
    float z = 0.0f;
    #pragma unroll
    for (int k = 0; k < 4; k++) {
        if (!ls[k]) z += __expf(xs[k] - mneg);
    }
    z = warp_sum(z);

    // ---- per-positive logsumexp: lse_j = m + log(e^-m + Z*e^{M - x_j - m}) ----
    float wl  = 0.0f;
    float pos = 0.0f;
    #pragma unroll
    for (int k = 0; k < 4; k++) {
        if (ls[k]) {
            float d = mneg - xs[k];            // finite even when mneg = -FLT_MAX
            float m = fmaxf(0.0f, d);
            wl  += m + logf(__expf(-m) + z * __expf(d - m));
            pos += 1.0f;
        }
    }

    bce = warp_sum(bce);
    wl  = warp_sum(wl);
    pos = warp_sum(pos);

    // ---- block reduction over the 8 warps ----
    __shared__ float s_bce[ROWS_PER_BLOCK];
    __shared__ float s_wl[ROWS_PER_BLOCK];
    __shared__ float s_pos[ROWS_PER_BLOCK];
    if (lane == 0) {
        s_bce[threadIdx.y] = bce;
        s_wl[threadIdx.y]  = wl;
        s_pos[threadIdx.y] = pos;
    }
    __syncthreads();
    if (threadIdx.y == 0 && lane == 0) {
        float b = 0.0f, w = 0.0f, p = 0.0f;
        #pragma unroll
        for (int i = 0; i < ROWS_PER_BLOCK; i++) {
            b += s_bce[i]; w += s_wl[i]; p += s_pos[i];
        }
        g_partial[blockIdx.x * 3 + 0] = b;
        g_partial[blockIdx.x * 3 + 1] = w;
        g_partial[blockIdx.x * 3 + 2] = p;
    }
}

// Kernel 2: single block reduces the 512 partial triples and writes the scalar.
__global__ void __launch_bounds__(512)
reduce_kernel(float* __restrict__ out) {
    __shared__ float s_b[512];
    __shared__ float s_w[512];
    __shared__ float s_p[512];
    int t = threadIdx.x;
    s_b[t] = g_partial[t * 3 + 0];
    s_w[t] = g_partial[t * 3 + 1];
    s_p[t] = g_partial[t * 3 + 2];
    __syncthreads();
    #pragma unroll
    for (int stride = 256; stride > 0; stride >>= 1) {
        if (t < stride) {
            s_b[t] += s_b[t + stride];
            s_w[t] += s_w[t + stride];
            s_p[t] += s_p[t + stride];
        }
        __syncthreads();
    }
    if (t == 0) {
        float bce_mean = s_b[0] / (float)(B_ROWS * C_COLS);
        float wlsep    = s_w[0] / s_p[0];
        out[0] = bce_mean + wlsep;
    }
}

extern "C" void kernel_launch(void* const* d_in, const int* in_sizes, int n_in,
                              void* d_out, int out_size) {
    (void)in_sizes; (void)n_in; (void)out_size;
    const float* x   = (const float*)d_in[0];
    const int*   tgt = (const int*)d_in[1];
    float*       out = (float*)d_out;

    dim3 blk(32, ROWS_PER_BLOCK);
    row_kernel<<<NBLOCKS, blk>>>(x, tgt);
    reduce_kernel<<<1, 512>>>(out);
}

// round 2
// speedup vs baseline: 1.2564x; 1.2564x over previous
#include <cuda_runtime.h>
#include <math.h>
#include <float.h>

#define B_ROWS 4096
#define C_COLS 128
#define WARPS_PER_BLOCK 16
#define NBLOCKS (B_ROWS / WARPS_PER_BLOCK)   // 256

// Per-block partials [bce, wlsep, pos] and completion counter.
__device__ float g_partial[NBLOCKS * 3];
__device__ unsigned int g_count;

__device__ __forceinline__ float softplusf(float t) {
    float a = fabsf(t);
    return fmaxf(t, 0.0f) + log1pf(__expf(-a));
}

__device__ __forceinline__ float warp_sum(float v) {
    #pragma unroll
    for (int o = 16; o > 0; o >>= 1)
        v += __shfl_xor_sync(0xFFFFFFFFu, v, o);
    return v;
}

__device__ __forceinline__ float warp_max(float v) {
    #pragma unroll
    for (int o = 16; o > 0; o >>= 1)
        v = fmaxf(v, __shfl_xor_sync(0xFFFFFFFFu, v, o));
    return v;
}

__global__ void __launch_bounds__(32 * WARPS_PER_BLOCK)
fused_kernel(const float* __restrict__ x, const int* __restrict__ tgt,
             float* __restrict__ out) {
    const int warp = threadIdx.y;
    const int lane = threadIdx.x;
    const int tid  = warp * 32 + lane;
    const int row  = blockIdx.x * WARPS_PER_BLOCK + warp;

    // ---- one LDG.128 per operand per warp: lane holds 4 consecutive cols ----
    const float4 xv = ((const float4*)(x   + (size_t)row * C_COLS))[lane];
    const int4   lv = ((const int4*)  (tgt + (size_t)row * C_COLS))[lane];
    float xs[4] = {xv.x, xv.y, xv.z, xv.w};
    int   ls[4] = {lv.x, lv.y, lv.z, lv.w};

    // ---- BCE + negative-class max ----
    float bce  = 0.0f;
    float mneg = -FLT_MAX;
    #pragma unroll
    for (int k = 0; k < 4; k++) {
        float t = ls[k] ? -xs[k] : xs[k];
        bce += softplusf(t);
        if (!ls[k]) mneg = fmaxf(mneg, xs[k]);
    }
    mneg = warp_max(mneg);

    // ---- Z = sum over negatives of exp(x_i - M) ----
    float z = 0.0f;
    #pragma unroll
    for (int k = 0; k < 4; k++)
        if (!ls[k]) z += __expf(xs[k] - mneg);
    z = warp_sum(z);

    // ---- per-positive lse_j = m + log(e^-m + Z*e^{M-x_j-m}), m=max(0,M-x_j) ----
    float wl = 0.0f, pos = 0.0f;
    #pragma unroll
    for (int k = 0; k < 4; k++) {
        if (ls[k]) {
            float d = mneg - xs[k];
            float m = fmaxf(0.0f, d);
            wl  += m + logf(__expf(-m) + z * __expf(d - m));
            pos += 1.0f;
        }
    }

    bce = warp_sum(bce);
    wl  = warp_sum(wl);
    pos = warp_sum(pos);

    // ---- block reduction over 16 warps ----
    __shared__ float s_b[WARPS_PER_BLOCK];
    __shared__ float s_w[WARPS_PER_BLOCK];
    __shared__ float s_p[WARPS_PER_BLOCK];
    if (lane == 0) { s_b[warp] = bce; s_w[warp] = wl; s_p[warp] = pos; }
    __syncthreads();

    __shared__ bool is_last;
    if (tid == 0) {
        float b = 0.0f, w = 0.0f, p = 0.0f;
        #pragma unroll
        for (int i = 0; i < WARPS_PER_BLOCK; i++) {
            b += s_b[i]; w += s_w[i]; p += s_p[i];
        }
        g_partial[blockIdx.x * 3 + 0] = b;
        g_partial[blockIdx.x * 3 + 1] = w;
        g_partial[blockIdx.x * 3 + 2] = p;
        __threadfence();
        unsigned int v = atomicAdd(&g_count, 1u);
        is_last = (v == (unsigned)(gridDim.x - 1));
    }
    __syncthreads();

    // ---- last block reduces all partials (fixed order -> deterministic) ----
    if (is_last) {
        __shared__ float r_b[NBLOCKS], r_w[NBLOCKS], r_p[NBLOCKS];
        const volatile float* gp = g_partial;
        if (tid < NBLOCKS) {
            r_b[tid] = gp[tid * 3 + 0];
            r_w[tid] = gp[tid * 3 + 1];
            r_p[tid] = gp[tid * 3 + 2];
        }
        __syncthreads();
        #pragma unroll
        for (int stride = NBLOCKS / 2; stride > 0; stride >>= 1) {
            if (tid < stride) {
                r_b[tid] += r_b[tid + stride];
                r_w[tid] += r_w[tid + stride];
                r_p[tid] += r_p[tid + stride];
            }
            __syncthreads();
        }
        if (tid == 0) {
            out[0] = r_b[0] / (float)(B_ROWS * C_COLS) + r_w[0] / r_p[0];
            g_count = 0;   // reset for next graph replay
        }
    }
}

extern "C" void kernel_launch(void* const* d_in, const int* in_sizes, int n_in,
                              void* d_out, int out_size) {
    (void)in_sizes; (void)n_in; (void)out_size;
    const float* x   = (const float*)d_in[0];
    const int*   tgt = (const int*)d_in[1];
    float*       out = (float*)d_out;

    dim3 blk(32, WARPS_PER_BLOCK);
    fused_kernel<<<NBLOCKS, blk>>>(x, tgt, out);
}